// round 2
// baseline (speedup 1.0000x reference)
#include <cuda_runtime.h>
#include <math.h>

#define B_ 8
#define C_ 384
#define HW_ 4096

// Scratch (device globals — no runtime allocation)
__device__ float g_buf0[B_ * C_ * HW_];   // xdw, later xi
__device__ float g_buf1[B_ * C_ * HW_];   // xs,  later y
__device__ float g_z[B_ * HW_ * C_];      // z token-major
__device__ float g_gate[C_ * HW_];        // spectral gate [c][n*64+k]
__device__ float g_W[64 * 64];            // DCT-II basis (Wh == Ww)

// ---------------------------------------------------------------------------
// DCT basis: W[n][x] = cos(n*(x+0.5)/64*pi) * sqrt(2/64), row 0 scaled 1/sqrt2
// ---------------------------------------------------------------------------
__global__ void k_dct_basis() {
    int n = blockIdx.x, x = threadIdx.x;
    float v = cosf((float)n * ((float)x + 0.5f) * (3.14159265358979323846f / 64.0f))
              * 0.17677669529663687f;
    if (n == 0) v *= 0.70710678118654752f;
    g_W[n * 64 + x] = v;
}

// ---------------------------------------------------------------------------
// Depthwise 3x3 conv (SAME) + bias. One block per (b,c) image.
// ---------------------------------------------------------------------------
__global__ void k_dwconv(const float* __restrict__ x,
                         const float* __restrict__ w,
                         const float* __restrict__ bias) {
    __shared__ float s[66 * 68];
    int bc = blockIdx.x;
    const float* xim = x + (size_t)bc * HW_;
    int tid = threadIdx.x;
    for (int i = tid; i < 66 * 66; i += 256) {
        int r = i / 66, cl = i % 66;
        int gh = r - 1, gw = cl - 1;
        float v = 0.0f;
        if ((unsigned)gh < 64u && (unsigned)gw < 64u) v = xim[gh * 64 + gw];
        s[r * 68 + cl] = v;
    }
    int c = bc % C_;
    const float* wp = w + c * 9;
    float w0 = wp[0], w1 = wp[1], w2 = wp[2];
    float w3 = wp[3], w4 = wp[4], w5 = wp[5];
    float w6 = wp[6], w7 = wp[7], w8 = wp[8];
    float bv = bias[c];
    __syncthreads();
    float* outp = g_buf0 + (size_t)bc * HW_;
    for (int p = tid; p < HW_; p += 256) {
        int h = p >> 6, ww = p & 63;
        const float* sp = s + h * 68 + ww;
        float acc = bv;
        acc = fmaf(sp[0],   w0, acc); acc = fmaf(sp[1],   w1, acc); acc = fmaf(sp[2],   w2, acc);
        acc = fmaf(sp[68],  w3, acc); acc = fmaf(sp[69],  w4, acc); acc = fmaf(sp[70],  w5, acc);
        acc = fmaf(sp[136], w6, acc); acc = fmaf(sp[137], w7, acc); acc = fmaf(sp[138], w8, acc);
        outp[p] = acc;
    }
}

// ---------------------------------------------------------------------------
// lin GEMM: xz[m][d] = sum_c xdw[c][m] * lin_w[d][c] + lin_b[d]
// A (xdw) is [K][M] per batch (K-major rows contiguous in m).
// d < 384 -> xs (NCHW in buf1, staged through smem for coalesced writes)
// d >= 384 -> z  (token-major, direct float4 writes)
// ---------------------------------------------------------------------------
__global__ void k_gemm_lin(const float* __restrict__ lw, const float* __restrict__ lb) {
    __shared__ float sA[16 * 68], sB[16 * 68], sC[64 * 68];
    int b = blockIdx.z;
    int m0 = blockIdx.x * 64, n0 = blockIdx.y * 64;
    const float* A = g_buf0 + (size_t)b * C_ * HW_;
    int tid = threadIdx.x, tx = tid & 15, ty = tid >> 4;
    float acc[4][4] = {};
    for (int kt = 0; kt < C_; kt += 16) {
        #pragma unroll
        for (int i = tid; i < 1024; i += 256) {
            int kk = i >> 6, mm = i & 63;
            sA[kk * 68 + mm] = A[(size_t)(kt + kk) * HW_ + m0 + mm];
        }
        #pragma unroll
        for (int i = tid; i < 1024; i += 256) {
            int nn = i >> 4, kk = i & 15;
            sB[kk * 68 + nn] = lw[(size_t)(n0 + nn) * C_ + kt + kk];
        }
        __syncthreads();
        #pragma unroll
        for (int kk = 0; kk < 16; kk++) {
            float4 a4 = *(const float4*)(sA + kk * 68 + ty * 4);
            float4 b4 = *(const float4*)(sB + kk * 68 + tx * 4);
            float av[4] = {a4.x, a4.y, a4.z, a4.w};
            float bv[4] = {b4.x, b4.y, b4.z, b4.w};
            #pragma unroll
            for (int i = 0; i < 4; i++)
                #pragma unroll
                for (int j = 0; j < 4; j++)
                    acc[i][j] = fmaf(av[i], bv[j], acc[i][j]);
        }
        __syncthreads();
    }
    if (n0 < C_) {  // xs half -> NCHW via smem stage
        #pragma unroll
        for (int i = 0; i < 4; i++)
            #pragma unroll
            for (int j = 0; j < 4; j++)
                sC[(tx * 4 + j) * 68 + ty * 4 + i] = acc[i][j];
        __syncthreads();
        float* xs = g_buf1 + (size_t)b * C_ * HW_;
        for (int i = tid; i < 4096; i += 256) {
            int nn = i >> 6, mm = i & 63;
            xs[(size_t)(n0 + nn) * HW_ + m0 + mm] = sC[nn * 68 + mm] + lb[n0 + nn];
        }
    } else {        // z half -> token-major direct
        float* zb = g_z + (size_t)b * HW_ * C_;
        float4 lb4 = *(const float4*)(lb + n0 + tx * 4);
        #pragma unroll
        for (int i = 0; i < 4; i++) {
            int m = m0 + ty * 4 + i;
            float4 v = make_float4(acc[i][0] + lb4.x, acc[i][1] + lb4.y,
                                   acc[i][2] + lb4.z, acc[i][3] + lb4.w);
            *(float4*)(zb + (size_t)m * C_ + (n0 - C_) + tx * 4) = v;
        }
    }
}

// ---------------------------------------------------------------------------
// gate GEMM: t[m][d] = relu(sum_c fe[m][c]*tok_w[d][c] + tok_b[d])
// gate[d][m] = cos(c0*t) + sin(c0*t)*(1+0.5*alpha)/c0
// A is token-major -> transposed smem staging.
// ---------------------------------------------------------------------------
__global__ void k_gate(const float* __restrict__ fe,
                       const float* __restrict__ tw,
                       const float* __restrict__ tb,
                       const float* __restrict__ cp,
                       const float* __restrict__ ap) {
    __shared__ float sA[16 * 68], sB[16 * 68], sC[64 * 68];
    int m0 = blockIdx.x * 64, n0 = blockIdx.y * 64;
    int tid = threadIdx.x, tx = tid & 15, ty = tid >> 4;
    float acc[4][4] = {};
    for (int kt = 0; kt < C_; kt += 16) {
        #pragma unroll
        for (int i = tid; i < 1024; i += 256) {
            int mm = i >> 4, kk = i & 15;
            sA[kk * 68 + mm] = fe[(size_t)(m0 + mm) * C_ + kt + kk];
        }
        #pragma unroll
        for (int i = tid; i < 1024; i += 256) {
            int nn = i >> 4, kk = i & 15;
            sB[kk * 68 + nn] = tw[(size_t)(n0 + nn) * C_ + kt + kk];
        }
        __syncthreads();
        #pragma unroll
        for (int kk = 0; kk < 16; kk++) {
            float4 a4 = *(const float4*)(sA + kk * 68 + ty * 4);
            float4 b4 = *(const float4*)(sB + kk * 68 + tx * 4);
            float av[4] = {a4.x, a4.y, a4.z, a4.w};
            float bv[4] = {b4.x, b4.y, b4.z, b4.w};
            #pragma unroll
            for (int i = 0; i < 4; i++)
                #pragma unroll
                for (int j = 0; j < 4; j++)
                    acc[i][j] = fmaf(av[i], bv[j], acc[i][j]);
        }
        __syncthreads();
    }
    #pragma unroll
    for (int i = 0; i < 4; i++)
        #pragma unroll
        for (int j = 0; j < 4; j++)
            sC[(tx * 4 + j) * 68 + ty * 4 + i] = acc[i][j];
    __syncthreads();
    float c0 = cp[0];
    float s1 = (1.0f + 0.5f * ap[0]) / c0;
    for (int i = tid; i < 4096; i += 256) {
        int nn = i >> 6, mm = i & 63;
        float t = sC[nn * 68 + mm] + tb[n0 + nn];
        t = fmaxf(t, 0.0f);
        float ct = c0 * t;
        g_gate[(size_t)(n0 + nn) * HW_ + m0 + mm] = cosf(ct) + sinf(ct) * s1;
    }
}

// ---------------------------------------------------------------------------
// Fused DCT -> gate -> inverse DCT per (b,c) image.
// xi = W^T (gate o (W X W^T)) W, all four 64^3 matmuls in smem.
// Transposes arranged so every compute access is row-major (bcast or float4).
// ---------------------------------------------------------------------------
__global__ void k_dct() {
    __shared__ float sW[64 * 64], sA[64 * 64], sB[64 * 64];
    int bc = blockIdx.x;
    int c = bc % C_;
    int tid = threadIdx.x, tx = tid & 15, ty = tid >> 4;
    const float* xim = g_buf1 + (size_t)bc * HW_;
    for (int i = tid; i < 4096; i += 256) { sW[i] = g_W[i]; sA[i] = xim[i]; }
    __syncthreads();

    float acc[4][4];

    // mm1: M1[n][w] = sum_h W[n][h] X[h][w]; store transposed sB[w][n]
    #pragma unroll
    for (int i = 0; i < 4; i++)
        #pragma unroll
        for (int j = 0; j < 4; j++) acc[i][j] = 0.0f;
    #pragma unroll 8
    for (int k = 0; k < 64; k++) {
        float a0 = sW[(ty * 4 + 0) * 64 + k];
        float a1 = sW[(ty * 4 + 1) * 64 + k];
        float a2 = sW[(ty * 4 + 2) * 64 + k];
        float a3 = sW[(ty * 4 + 3) * 64 + k];
        float4 b4 = *(const float4*)(sA + k * 64 + tx * 4);
        float bv[4] = {b4.x, b4.y, b4.z, b4.w};
        #pragma unroll
        for (int j = 0; j < 4; j++) {
            acc[0][j] = fmaf(a0, bv[j], acc[0][j]);
            acc[1][j] = fmaf(a1, bv[j], acc[1][j]);
            acc[2][j] = fmaf(a2, bv[j], acc[2][j]);
            acc[3][j] = fmaf(a3, bv[j], acc[3][j]);
        }
    }
    #pragma unroll
    for (int i = 0; i < 4; i++)
        #pragma unroll
        for (int j = 0; j < 4; j++)
            sB[(tx * 4 + j) * 64 + ty * 4 + i] = acc[i][j];
    __syncthreads();

    // mm2: XdT[k][n] = sum_w W[k][w] M1T[w][n]; gate; store sA[k][n]
    #pragma unroll
    for (int i = 0; i < 4; i++)
        #pragma unroll
        for (int j = 0; j < 4; j++) acc[i][j] = 0.0f;
    #pragma unroll 8
    for (int w = 0; w < 64; w++) {
        float a0 = sW[(ty * 4 + 0) * 64 + w];
        float a1 = sW[(ty * 4 + 1) * 64 + w];
        float a2 = sW[(ty * 4 + 2) * 64 + w];
        float a3 = sW[(ty * 4 + 3) * 64 + w];
        float4 b4 = *(const float4*)(sB + w * 64 + tx * 4);
        float bv[4] = {b4.x, b4.y, b4.z, b4.w};
        #pragma unroll
        for (int j = 0; j < 4; j++) {
            acc[0][j] = fmaf(a0, bv[j], acc[0][j]);
            acc[1][j] = fmaf(a1, bv[j], acc[1][j]);
            acc[2][j] = fmaf(a2, bv[j], acc[2][j]);
            acc[3][j] = fmaf(a3, bv[j], acc[3][j]);
        }
    }
    {
        const float* gb = g_gate + (size_t)c * HW_;
        #pragma unroll
        for (int j = 0; j < 4; j++) {
            float4 g4 = *(const float4*)(gb + (tx * 4 + j) * 64 + ty * 4);
            acc[0][j] *= g4.x; acc[1][j] *= g4.y; acc[2][j] *= g4.z; acc[3][j] *= g4.w;
        }
    }
    #pragma unroll
    for (int i = 0; i < 4; i++)
        *(float4*)(sA + (ty * 4 + i) * 64 + tx * 4) =
            make_float4(acc[i][0], acc[i][1], acc[i][2], acc[i][3]);
    __syncthreads();

    // mm3: M2T[k][h] = sum_n FT[k][n] W[n][h]; store sB[k][h]
    #pragma unroll
    for (int i = 0; i < 4; i++)
        #pragma unroll
        for (int j = 0; j < 4; j++) acc[i][j] = 0.0f;
    #pragma unroll 8
    for (int n = 0; n < 64; n++) {
        float a0 = sA[(ty * 4 + 0) * 64 + n];
        float a1 = sA[(ty * 4 + 1) * 64 + n];
        float a2 = sA[(ty * 4 + 2) * 64 + n];
        float a3 = sA[(ty * 4 + 3) * 64 + n];
        float4 b4 = *(const float4*)(sW + n * 64 + tx * 4);
        float bv[4] = {b4.x, b4.y, b4.z, b4.w};
        #pragma unroll
        for (int j = 0; j < 4; j++) {
            acc[0][j] = fmaf(a0, bv[j], acc[0][j]);
            acc[1][j] = fmaf(a1, bv[j], acc[1][j]);
            acc[2][j] = fmaf(a2, bv[j], acc[2][j]);
            acc[3][j] = fmaf(a3, bv[j], acc[3][j]);
        }
    }
    #pragma unroll
    for (int i = 0; i < 4; i++)
        *(float4*)(sB + (ty * 4 + i) * 64 + tx * 4) =
            make_float4(acc[i][0], acc[i][1], acc[i][2], acc[i][3]);
    __syncthreads();

    // mm4: xi[h][w] = sum_k M2T[k][h] W[k][w]; write global
    #pragma unroll
    for (int i = 0; i < 4; i++)
        #pragma unroll
        for (int j = 0; j < 4; j++) acc[i][j] = 0.0f;
    #pragma unroll 8
    for (int k = 0; k < 64; k++) {
        float4 a4 = *(const float4*)(sB + k * 64 + ty * 4);
        float4 b4 = *(const float4*)(sW + k * 64 + tx * 4);
        float av[4] = {a4.x, a4.y, a4.z, a4.w};
        float bv[4] = {b4.x, b4.y, b4.z, b4.w};
        #pragma unroll
        for (int i = 0; i < 4; i++)
            #pragma unroll
            for (int j = 0; j < 4; j++)
                acc[i][j] = fmaf(av[i], bv[j], acc[i][j]);
    }
    float* xo = g_buf0 + (size_t)bc * HW_;
    #pragma unroll
    for (int i = 0; i < 4; i++)
        *(float4*)(xo + (ty * 4 + i) * 64 + tx * 4) =
            make_float4(acc[i][0], acc[i][1], acc[i][2], acc[i][3]);
}

// ---------------------------------------------------------------------------
// LayerNorm over channels + SiLU(z) gate. 16 tokens per block of 128 threads.
// xi is NCHW (strided per token) -> transpose tile in smem.
// ---------------------------------------------------------------------------
__global__ void k_ln(const float* __restrict__ lng, const float* __restrict__ lnb) {
    __shared__ float s[C_ * 17];
    int tid = threadIdx.x;
    int mglob = blockIdx.x * 16;
    int b = mglob >> 12;
    int mloc = mglob & 4095;
    const float* xi = g_buf0 + (size_t)b * C_ * HW_ + mloc;
    for (int i = tid; i < C_ * 16; i += 128) {
        int cc = i >> 4, t = i & 15;
        s[cc * 17 + t] = xi[(size_t)cc * HW_ + t];
    }
    __syncthreads();
    int tk = tid >> 3, g = tid & 7;
    float sum = 0.0f, ss = 0.0f;
    #pragma unroll 8
    for (int ii = 0; ii < 48; ii++) {
        int cc = g + ii * 8;
        float v = s[cc * 17 + tk];
        sum += v; ss += v * v;
    }
    #pragma unroll
    for (int off = 4; off; off >>= 1) {
        sum += __shfl_down_sync(0xffffffffu, sum, off);
        ss  += __shfl_down_sync(0xffffffffu, ss,  off);
    }
    int lane = tid & 31;
    int src = lane & ~7;
    sum = __shfl_sync(0xffffffffu, sum, src);
    ss  = __shfl_sync(0xffffffffu, ss,  src);
    float mu = sum * (1.0f / 384.0f);
    float var = ss * (1.0f / 384.0f) - mu * mu;
    float rstd = rsqrtf(fmaxf(var, 0.0f) + 1e-5f);

    int mt = mloc + tk;
    const float* zp = g_z + ((size_t)b * HW_ + mt) * C_;
    float* yp = g_buf1 + ((size_t)b * HW_ + mt) * C_;
    #pragma unroll 4
    for (int ii = 0; ii < 12; ii++) {
        int c0 = g * 48 + ii * 4;
        float4 zv = *(const float4*)(zp + c0);
        float4 gg = *(const float4*)(lng + c0);
        float4 bb = *(const float4*)(lnb + c0);
        float y0 = (s[(c0 + 0) * 17 + tk] - mu) * rstd * gg.x + bb.x;
        float y1 = (s[(c0 + 1) * 17 + tk] - mu) * rstd * gg.y + bb.y;
        float y2 = (s[(c0 + 2) * 17 + tk] - mu) * rstd * gg.z + bb.z;
        float y3 = (s[(c0 + 3) * 17 + tk] - mu) * rstd * gg.w + bb.w;
        y0 *= zv.x / (1.0f + __expf(-zv.x));
        y1 *= zv.y / (1.0f + __expf(-zv.y));
        y2 *= zv.z / (1.0f + __expf(-zv.z));
        y3 *= zv.w / (1.0f + __expf(-zv.w));
        *(float4*)(yp + c0) = make_float4(y0, y1, y2, y3);
    }
}

// ---------------------------------------------------------------------------
// out GEMM: out[d][m] = sum_c y[m][c]*out_w[d][c] + out_b[d], NCHW output.
// A token-major -> transposed staging; epilogue staged via smem.
// ---------------------------------------------------------------------------
__global__ void k_gemm_out(const float* __restrict__ ow,
                           const float* __restrict__ ob,
                           float* __restrict__ out) {
    __shared__ float sA[16 * 68], sB[16 * 68], sC[64 * 68];
    int b = blockIdx.z;
    int m0 = blockIdx.x * 64, n0 = blockIdx.y * 64;
    const float* A = g_buf1 + (size_t)b * HW_ * C_;
    int tid = threadIdx.x, tx = tid & 15, ty = tid >> 4;
    float acc[4][4] = {};
    for (int kt = 0; kt < C_; kt += 16) {
        #pragma unroll
        for (int i = tid; i < 1024; i += 256) {
            int mm = i >> 4, kk = i & 15;
            sA[kk * 68 + mm] = A[(size_t)(m0 + mm) * C_ + kt + kk];
        }
        #pragma unroll
        for (int i = tid; i < 1024; i += 256) {
            int nn = i >> 4, kk = i & 15;
            sB[kk * 68 + nn] = ow[(size_t)(n0 + nn) * C_ + kt + kk];
        }
        __syncthreads();
        #pragma unroll
        for (int kk = 0; kk < 16; kk++) {
            float4 a4 = *(const float4*)(sA + kk * 68 + ty * 4);
            float4 b4 = *(const float4*)(sB + kk * 68 + tx * 4);
            float av[4] = {a4.x, a4.y, a4.z, a4.w};
            float bv[4] = {b4.x, b4.y, b4.z, b4.w};
            #pragma unroll
            for (int i = 0; i < 4; i++)
                #pragma unroll
                for (int j = 0; j < 4; j++)
                    acc[i][j] = fmaf(av[i], bv[j], acc[i][j]);
        }
        __syncthreads();
    }
    #pragma unroll
    for (int i = 0; i < 4; i++)
        #pragma unroll
        for (int j = 0; j < 4; j++)
            sC[(tx * 4 + j) * 68 + ty * 4 + i] = acc[i][j];
    __syncthreads();
    float* ob_out = out + (size_t)b * C_ * HW_;
    for (int i = tid; i < 4096; i += 256) {
        int nn = i >> 6, mm = i & 63;
        ob_out[(size_t)(n0 + nn) * HW_ + m0 + mm] = sC[nn * 68 + mm] + ob[n0 + nn];
    }
}

// ---------------------------------------------------------------------------
extern "C" void kernel_launch(void* const* d_in, const int* in_sizes, int n_in,
                              void* d_out, int out_size) {
    const float* x     = (const float*)d_in[0];
    const float* fe    = (const float*)d_in[1];
    const float* dw_w  = (const float*)d_in[2];
    const float* dw_b  = (const float*)d_in[3];
    const float* lin_w = (const float*)d_in[4];
    const float* lin_b = (const float*)d_in[5];
    const float* tok_w = (const float*)d_in[6];
    const float* tok_b = (const float*)d_in[7];
    const float* cc    = (const float*)d_in[8];
    const float* alpha = (const float*)d_in[9];
    const float* ln_g  = (const float*)d_in[10];
    const float* ln_b  = (const float*)d_in[11];
    const float* out_w = (const float*)d_in[12];
    const float* out_b = (const float*)d_in[13];
    float* out = (float*)d_out;

    k_dct_basis<<<64, 64>>>();
    k_dwconv<<<B_ * C_, 256>>>(x, dw_w, dw_b);
    k_gate<<<dim3(64, 6, 1), 256>>>(fe, tok_w, tok_b, cc, alpha);
    k_gemm_lin<<<dim3(64, 12, B_), 256>>>(lin_w, lin_b);
    k_dct<<<B_ * C_, 256>>>();
    k_ln<<<(B_ * HW_) / 16, 128>>>(ln_g, ln_b);
    k_gemm_out<<<dim3(64, 6, B_), 256>>>(out_w, out_b, out);
}

// round 3
// speedup vs baseline: 2.7282x; 2.7282x over previous
#include <cuda_runtime.h>
#include <math.h>
#include <stdint.h>

#define B_ 8
#define C_ 384
#define HW_ 4096

// Scratch (device globals — no runtime allocation)
__device__ float g_buf0[B_ * C_ * HW_];   // xdw, later xi
__device__ float g_buf1[B_ * C_ * HW_];   // xs,  later y
__device__ float g_z[B_ * HW_ * C_];      // z token-major
__device__ float g_gate[C_ * HW_];        // spectral gate [c][n*64+k]
__device__ float g_W[64 * 64];            // DCT-II basis (Wh == Ww)

// ---------------------------------------------------------------------------
// helpers: tf32 conversion + m16n8k8 tf32 mma
// ---------------------------------------------------------------------------
__device__ __forceinline__ uint32_t f2tf(float f) {
    uint32_t u;
    asm("cvt.rna.tf32.f32 %0, %1;" : "=r"(u) : "f"(f));
    return u;
}

__device__ __forceinline__ void mma8(float* c, uint32_t a0, uint32_t a1,
                                     uint32_t a2, uint32_t a3,
                                     uint32_t b0, uint32_t b1) {
    asm volatile(
        "mma.sync.aligned.m16n8k8.row.col.f32.tf32.tf32.f32 "
        "{%0,%1,%2,%3}, {%4,%5,%6,%7}, {%8,%9}, {%0,%1,%2,%3};"
        : "+f"(c[0]), "+f"(c[1]), "+f"(c[2]), "+f"(c[3])
        : "r"(a0), "r"(a1), "r"(a2), "r"(a3), "r"(b0), "r"(b1));
}

// ---------------------------------------------------------------------------
// DCT basis
// ---------------------------------------------------------------------------
__global__ void k_dct_basis() {
    int n = blockIdx.x, x = threadIdx.x;
    float v = cosf((float)n * ((float)x + 0.5f) * (3.14159265358979323846f / 64.0f))
              * 0.17677669529663687f;
    if (n == 0) v *= 0.70710678118654752f;
    g_W[n * 64 + x] = v;
}

// ---------------------------------------------------------------------------
// Depthwise 3x3 conv (SAME) + bias. One block per (b,c) image.
// ---------------------------------------------------------------------------
__global__ void k_dwconv(const float* __restrict__ x,
                         const float* __restrict__ w,
                         const float* __restrict__ bias) {
    __shared__ float s[66 * 68];
    int bc = blockIdx.x;
    const float* xim = x + (size_t)bc * HW_;
    int tid = threadIdx.x;
    for (int i = tid; i < 66 * 66; i += 256) {
        int r = i / 66, cl = i % 66;
        int gh = r - 1, gw = cl - 1;
        float v = 0.0f;
        if ((unsigned)gh < 64u && (unsigned)gw < 64u) v = xim[gh * 64 + gw];
        s[r * 68 + cl] = v;
    }
    int c = bc % C_;
    const float* wp = w + c * 9;
    float w0 = wp[0], w1 = wp[1], w2 = wp[2];
    float w3 = wp[3], w4 = wp[4], w5 = wp[5];
    float w6 = wp[6], w7 = wp[7], w8 = wp[8];
    float bv = bias[c];
    __syncthreads();
    float* outp = g_buf0 + (size_t)bc * HW_;
    for (int p = tid; p < HW_; p += 256) {
        int h = p >> 6, ww = p & 63;
        const float* sp = s + h * 68 + ww;
        float acc = bv;
        acc = fmaf(sp[0],   w0, acc); acc = fmaf(sp[1],   w1, acc); acc = fmaf(sp[2],   w2, acc);
        acc = fmaf(sp[68],  w3, acc); acc = fmaf(sp[69],  w4, acc); acc = fmaf(sp[70],  w5, acc);
        acc = fmaf(sp[136], w6, acc); acc = fmaf(sp[137], w7, acc); acc = fmaf(sp[138], w8, acc);
        outp[p] = acc;
    }
}

// ---------------------------------------------------------------------------
// Shared tf32 GEMM core. Block tile 128(M) x 64(N), K=384 in chunks of 32.
// 256 threads = 8 warps as 4(m) x 2(n); warp tile 32x32 (2 m-frags x 4 n-frags).
// smem A: [128][36] tf32 (stride 36 -> conflict-free fragment reads),
// smem B: [64][36].
// AMODE 0: A gmem layout [K][M] (m contiguous, ld = lda)
// AMODE 1: A gmem layout [M][K] (k contiguous, ld = lda)
// B gmem layout [N][K], k contiguous (ld = 384).
// ---------------------------------------------------------------------------
#define SMEM_GEMM_BYTES 34816   // max(sA+sB = 27648, sC variants <= 34816)

template<int AMODE>
__device__ __forceinline__ void gemm_core(const float* __restrict__ Ag, int lda,
                                          const float* __restrict__ Bg,
                                          int m0, int n0, int tid,
                                          char* sm, float acc[2][4][4]) {
    uint32_t* sA = (uint32_t*)sm;            // 128*36
    uint32_t* sB = sA + 128 * 36;            // 64*36
    int lane = tid & 31, g = lane >> 2, t4 = lane & 3;
    int warp = tid >> 5, wm = warp & 3, wn = warp >> 2;

    for (int kt = 0; kt < C_; kt += 32) {
        if (AMODE == 0) {
            #pragma unroll
            for (int i = tid; i < 1024; i += 256) {
                int mm = i & 127, k4 = i >> 7;
                const float* p = Ag + (size_t)(kt + 4 * k4) * lda + m0 + mm;
                uint4 v;
                v.x = f2tf(p[0]);
                v.y = f2tf(p[lda]);
                v.z = f2tf(p[2 * lda]);
                v.w = f2tf(p[3 * lda]);
                *(uint4*)(sA + mm * 36 + 4 * k4) = v;
            }
        } else {
            #pragma unroll
            for (int i = tid; i < 1024; i += 256) {
                int k4 = i & 7, mm = i >> 3;
                float4 f = *(const float4*)(Ag + (size_t)(m0 + mm) * lda + kt + 4 * k4);
                uint4 v;
                v.x = f2tf(f.x); v.y = f2tf(f.y); v.z = f2tf(f.z); v.w = f2tf(f.w);
                *(uint4*)(sA + mm * 36 + 4 * k4) = v;
            }
        }
        #pragma unroll
        for (int i = tid; i < 512; i += 256) {
            int k4 = i & 7, nn = i >> 3;
            float4 f = *(const float4*)(Bg + (size_t)(n0 + nn) * C_ + kt + 4 * k4);
            uint4 v;
            v.x = f2tf(f.x); v.y = f2tf(f.y); v.z = f2tf(f.z); v.w = f2tf(f.w);
            *(uint4*)(sB + nn * 36 + 4 * k4) = v;
        }
        __syncthreads();
        #pragma unroll
        for (int k8 = 0; k8 < 4; k8++) {
            uint32_t a[2][4];
            #pragma unroll
            for (int mf = 0; mf < 2; mf++) {
                const uint32_t* pa = sA + (wm * 32 + mf * 16 + g) * 36 + k8 * 8 + t4;
                a[mf][0] = pa[0];
                a[mf][1] = pa[8 * 36];
                a[mf][2] = pa[4];
                a[mf][3] = pa[8 * 36 + 4];
            }
            #pragma unroll
            for (int nf = 0; nf < 4; nf++) {
                const uint32_t* pb = sB + (wn * 32 + nf * 8 + g) * 36 + k8 * 8 + t4;
                uint32_t b0 = pb[0], b1 = pb[4];
                mma8(acc[0][nf], a[0][0], a[0][1], a[0][2], a[0][3], b0, b1);
                mma8(acc[1][nf], a[1][0], a[1][1], a[1][2], a[1][3], b0, b1);
            }
        }
        __syncthreads();
    }
}

// Stage warp-tile accumulators into sC as [n][m], stride 132 (conflict-free).
__device__ __forceinline__ void stage_nchw(float* sC, float acc[2][4][4], int tid) {
    int lane = tid & 31, g = lane >> 2, t4 = lane & 3;
    int warp = tid >> 5, wm = warp & 3, wn = warp >> 2;
    #pragma unroll
    for (int mf = 0; mf < 2; mf++) {
        int r = wm * 32 + mf * 16 + g;
        #pragma unroll
        for (int nf = 0; nf < 4; nf++) {
            int cc = wn * 32 + nf * 8 + 2 * t4;
            sC[cc * 132 + r]           = acc[mf][nf][0];
            sC[(cc + 1) * 132 + r]     = acc[mf][nf][1];
            sC[cc * 132 + r + 8]       = acc[mf][nf][2];
            sC[(cc + 1) * 132 + r + 8] = acc[mf][nf][3];
        }
    }
}

// ---------------------------------------------------------------------------
// lin GEMM: xz[m][d] = sum_c xdw[c][m]*lin_w[d][c] + lin_b[d]
// ---------------------------------------------------------------------------
__global__ void __launch_bounds__(256) k_lin_mma(const float* __restrict__ lw,
                                                const float* __restrict__ lb) {
    __shared__ __align__(16) char sm[SMEM_GEMM_BYTES];
    int tid = threadIdx.x;
    int b = blockIdx.z, m0 = blockIdx.x * 128, n0 = blockIdx.y * 64;
    float acc[2][4][4];
    #pragma unroll
    for (int i = 0; i < 2; i++)
        #pragma unroll
        for (int j = 0; j < 4; j++)
            #pragma unroll
            for (int k = 0; k < 4; k++) acc[i][j][k] = 0.0f;

    gemm_core<0>(g_buf0 + (size_t)b * C_ * HW_, HW_, lw, m0, n0, tid, sm, acc);

    if (n0 < C_) {
        // xs half -> NCHW
        float* sC = (float*)sm;
        stage_nchw(sC, acc, tid);
        __syncthreads();
        float* xs = g_buf1 + (size_t)b * C_ * HW_;
        for (int i = tid; i < 8192; i += 256) {
            int nn = i >> 7, mm = i & 127;
            xs[(size_t)(n0 + nn) * HW_ + m0 + mm] = sC[nn * 132 + mm] + lb[n0 + nn];
        }
    } else {
        // z half -> token-major [m][C]
        float* sC = (float*)sm;  // [128][68]
        int lane = tid & 31, g = lane >> 2, t4 = lane & 3;
        int warp = tid >> 5, wm = warp & 3, wn = warp >> 2;
        #pragma unroll
        for (int mf = 0; mf < 2; mf++) {
            int r = wm * 32 + mf * 16 + g;
            #pragma unroll
            for (int nf = 0; nf < 4; nf++) {
                int cc = wn * 32 + nf * 8 + 2 * t4;
                *(float2*)(sC + r * 68 + cc)       = make_float2(acc[mf][nf][0], acc[mf][nf][1]);
                *(float2*)(sC + (r + 8) * 68 + cc) = make_float2(acc[mf][nf][2], acc[mf][nf][3]);
            }
        }
        __syncthreads();
        float* zb = g_z + (size_t)b * HW_ * C_;
        for (int i = tid; i < 2048; i += 256) {
            int q = i & 15, mm = i >> 4;
            float4 v = *(float4*)(sC + mm * 68 + 4 * q);
            float4 bb = *(const float4*)(lb + n0 + 4 * q);
            v.x += bb.x; v.y += bb.y; v.z += bb.z; v.w += bb.w;
            *(float4*)(zb + (size_t)(m0 + mm) * C_ + (n0 - C_) + 4 * q) = v;
        }
    }
}

// ---------------------------------------------------------------------------
// gate GEMM: t = relu(fe @ tok_w^T + tok_b); gate = cos(c*t)+sin(c*t)*(1+.5a)/c
// ---------------------------------------------------------------------------
__global__ void __launch_bounds__(256) k_gate_mma(const float* __restrict__ fe,
                                                 const float* __restrict__ tw,
                                                 const float* __restrict__ tb,
                                                 const float* __restrict__ cp,
                                                 const float* __restrict__ ap) {
    __shared__ __align__(16) char sm[SMEM_GEMM_BYTES];
    int tid = threadIdx.x;
    int m0 = blockIdx.x * 128, n0 = blockIdx.y * 64;
    float acc[2][4][4];
    #pragma unroll
    for (int i = 0; i < 2; i++)
        #pragma unroll
        for (int j = 0; j < 4; j++)
            #pragma unroll
            for (int k = 0; k < 4; k++) acc[i][j][k] = 0.0f;

    gemm_core<1>(fe, C_, tw, m0, n0, tid, sm, acc);

    float* sC = (float*)sm;
    stage_nchw(sC, acc, tid);
    __syncthreads();
    float c0 = cp[0];
    float s1 = (1.0f + 0.5f * ap[0]) / c0;
    for (int i = tid; i < 8192; i += 256) {
        int nn = i >> 7, mm = i & 127;
        float t = sC[nn * 132 + mm] + tb[n0 + nn];
        t = fmaxf(t, 0.0f);
        float ct = c0 * t;
        g_gate[(size_t)(n0 + nn) * HW_ + m0 + mm] = cosf(ct) + sinf(ct) * s1;
    }
}

// ---------------------------------------------------------------------------
// out GEMM: out[d][m] = sum_c y[m][c]*out_w[d][c] + out_b[d]
// ---------------------------------------------------------------------------
__global__ void __launch_bounds__(256) k_out_mma(const float* __restrict__ ow,
                                                const float* __restrict__ ob,
                                                float* __restrict__ out) {
    __shared__ __align__(16) char sm[SMEM_GEMM_BYTES];
    int tid = threadIdx.x;
    int b = blockIdx.z, m0 = blockIdx.x * 128, n0 = blockIdx.y * 64;
    float acc[2][4][4];
    #pragma unroll
    for (int i = 0; i < 2; i++)
        #pragma unroll
        for (int j = 0; j < 4; j++)
            #pragma unroll
            for (int k = 0; k < 4; k++) acc[i][j][k] = 0.0f;

    gemm_core<1>(g_buf1 + (size_t)b * HW_ * C_, C_, ow, m0, n0, tid, sm, acc);

    float* sC = (float*)sm;
    stage_nchw(sC, acc, tid);
    __syncthreads();
    float* op = out + (size_t)b * C_ * HW_;
    for (int i = tid; i < 8192; i += 256) {
        int nn = i >> 7, mm = i & 127;
        op[(size_t)(n0 + nn) * HW_ + m0 + mm] = sC[nn * 132 + mm] + ob[n0 + nn];
    }
}

// ---------------------------------------------------------------------------
// Fused DCT -> gate -> iDCT per (b,c) image, tf32 mma.
// Tiles 64x64 tf32 in dynamic smem, stride 76 (conflict-free for both A and
// B fragment patterns). 8 warps: warp = (wm = warp&3 -> 16 rows, wn = warp>>2
// -> 32 cols as 4 n-frags).
// ---------------------------------------------------------------------------
#define DCT_STRIDE 76
#define DCT_TILE (64 * DCT_STRIDE)
#define DCT_SMEM_BYTES (3 * DCT_TILE * 4)

__device__ __forceinline__ void dct_mm(const uint32_t* __restrict__ pA,
                                       const uint32_t* __restrict__ pB,
                                       float acc[4][4], int r, int nb,
                                       int g, int t4) {
    #pragma unroll
    for (int nf = 0; nf < 4; nf++)
        #pragma unroll
        for (int j = 0; j < 4; j++) acc[nf][j] = 0.0f;
    #pragma unroll
    for (int k8 = 0; k8 < 8; k8++) {
        uint32_t a0 = pA[r * DCT_STRIDE + k8 * 8 + t4];
        uint32_t a1 = pA[(r + 8) * DCT_STRIDE + k8 * 8 + t4];
        uint32_t a2 = pA[r * DCT_STRIDE + k8 * 8 + t4 + 4];
        uint32_t a3 = pA[(r + 8) * DCT_STRIDE + k8 * 8 + t4 + 4];
        #pragma unroll
        for (int nf = 0; nf < 4; nf++) {
            int n = nb + nf * 8 + g;
            uint32_t b0 = pB[(k8 * 8 + t4) * DCT_STRIDE + n];
            uint32_t b1 = pB[(k8 * 8 + t4 + 4) * DCT_STRIDE + n];
            mma8(acc[nf], a0, a1, a2, a3, b0, b1);
        }
    }
}

__global__ void __launch_bounds__(256) k_dct_mma() {
    extern __shared__ uint32_t dsm[];
    uint32_t* tW = dsm;
    uint32_t* tA = dsm + DCT_TILE;
    uint32_t* tB = dsm + 2 * DCT_TILE;
    int bc = blockIdx.x;
    int c = bc % C_;
    int tid = threadIdx.x;
    const float* xim = g_buf1 + (size_t)bc * HW_;
    for (int i = tid; i < 4096; i += 256) {
        int h = i >> 6, w = i & 63;
        tW[h * DCT_STRIDE + w] = f2tf(g_W[i]);
        tA[h * DCT_STRIDE + w] = f2tf(xim[i]);
    }
    __syncthreads();

    int lane = tid & 31, g = lane >> 2, t4 = lane & 3;
    int warp = tid >> 5, wm = warp & 3, wn = warp >> 2;
    int r = wm * 16 + g, nb = wn * 32;
    float acc[4][4];

    // mm1: M1[n][w] = sum_h W[n][h] X[h][w]  -> store transposed tB[w][n]
    dct_mm(tW, tA, acc, r, nb, g, t4);
    #pragma unroll
    for (int nf = 0; nf < 4; nf++) {
        int cc = nb + nf * 8 + 2 * t4;
        tB[cc * DCT_STRIDE + r]           = f2tf(acc[nf][0]);
        tB[(cc + 1) * DCT_STRIDE + r]     = f2tf(acc[nf][1]);
        tB[cc * DCT_STRIDE + r + 8]       = f2tf(acc[nf][2]);
        tB[(cc + 1) * DCT_STRIDE + r + 8] = f2tf(acc[nf][3]);
    }
    __syncthreads();

    // mm2: XdT[k][n] = sum_w W[k][w] M1T[w][n]; gate; store tA[k][n]
    dct_mm(tW, tB, acc, r, nb, g, t4);
    {
        const float* gp = g_gate + (size_t)c * HW_;
        #pragma unroll
        for (int nf = 0; nf < 4; nf++) {
            int cc = nb + nf * 8 + 2 * t4;
            float g0 = gp[cc * 64 + r];
            float g1 = gp[(cc + 1) * 64 + r];
            float g2 = gp[cc * 64 + r + 8];
            float g3 = gp[(cc + 1) * 64 + r + 8];
            tA[r * DCT_STRIDE + cc]           = f2tf(acc[nf][0] * g0);
            tA[r * DCT_STRIDE + cc + 1]       = f2tf(acc[nf][1] * g1);
            tA[(r + 8) * DCT_STRIDE + cc]     = f2tf(acc[nf][2] * g2);
            tA[(r + 8) * DCT_STRIDE + cc + 1] = f2tf(acc[nf][3] * g3);
        }
    }
    __syncthreads();

    // mm3: M2T[k][h] = sum_n F[k][n] W[n][h] -> store transposed tB[h][k]
    dct_mm(tA, tW, acc, r, nb, g, t4);
    #pragma unroll
    for (int nf = 0; nf < 4; nf++) {
        int cc = nb + nf * 8 + 2 * t4;
        tB[cc * DCT_STRIDE + r]           = f2tf(acc[nf][0]);
        tB[(cc + 1) * DCT_STRIDE + r]     = f2tf(acc[nf][1]);
        tB[cc * DCT_STRIDE + r + 8]       = f2tf(acc[nf][2]);
        tB[(cc + 1) * DCT_STRIDE + r + 8] = f2tf(acc[nf][3]);
    }
    __syncthreads();

    // mm4: xi[h][w] = sum_k M2T[k][h] W[k][w] -> gmem
    dct_mm(tB, tW, acc, r, nb, g, t4);
    float* xo = g_buf0 + (size_t)bc * HW_;
    #pragma unroll
    for (int nf = 0; nf < 4; nf++) {
        int cc = nb + nf * 8 + 2 * t4;
        *(float2*)(xo + r * 64 + cc)       = make_float2(acc[nf][0], acc[nf][1]);
        *(float2*)(xo + (r + 8) * 64 + cc) = make_float2(acc[nf][2], acc[nf][3]);
    }
}

// ---------------------------------------------------------------------------
// LayerNorm over channels + SiLU(z) gate. 16 tokens per block of 128 threads.
// ---------------------------------------------------------------------------
__global__ void k_ln(const float* __restrict__ lng, const float* __restrict__ lnb) {
    __shared__ float s[C_ * 17];
    int tid = threadIdx.x;
    int mglob = blockIdx.x * 16;
    int b = mglob >> 12;
    int mloc = mglob & 4095;
    const float* xi = g_buf0 + (size_t)b * C_ * HW_ + mloc;
    for (int i = tid; i < C_ * 16; i += 128) {
        int cc = i >> 4, t = i & 15;
        s[cc * 17 + t] = xi[(size_t)cc * HW_ + t];
    }
    __syncthreads();
    int tk = tid >> 3, g = tid & 7;
    float sum = 0.0f, ss = 0.0f;
    #pragma unroll 8
    for (int ii = 0; ii < 48; ii++) {
        int cc = g + ii * 8;
        float v = s[cc * 17 + tk];
        sum += v; ss += v * v;
    }
    #pragma unroll
    for (int off = 4; off; off >>= 1) {
        sum += __shfl_down_sync(0xffffffffu, sum, off);
        ss  += __shfl_down_sync(0xffffffffu, ss,  off);
    }
    int lane = tid & 31;
    int src = lane & ~7;
    sum = __shfl_sync(0xffffffffu, sum, src);
    ss  = __shfl_sync(0xffffffffu, ss,  src);
    float mu = sum * (1.0f / 384.0f);
    float var = ss * (1.0f / 384.0f) - mu * mu;
    float rstd = rsqrtf(fmaxf(var, 0.0f) + 1e-5f);

    int mt = mloc + tk;
    const float* zp = g_z + ((size_t)b * HW_ + mt) * C_;
    float* yp = g_buf1 + ((size_t)b * HW_ + mt) * C_;
    #pragma unroll 4
    for (int ii = 0; ii < 12; ii++) {
        int c0 = g * 48 + ii * 4;
        float4 zv = *(const float4*)(zp + c0);
        float4 gg = *(const float4*)(lng + c0);
        float4 bb = *(const float4*)(lnb + c0);
        float y0 = (s[(c0 + 0) * 17 + tk] - mu) * rstd * gg.x + bb.x;
        float y1 = (s[(c0 + 1) * 17 + tk] - mu) * rstd * gg.y + bb.y;
        float y2 = (s[(c0 + 2) * 17 + tk] - mu) * rstd * gg.z + bb.z;
        float y3 = (s[(c0 + 3) * 17 + tk] - mu) * rstd * gg.w + bb.w;
        y0 *= zv.x / (1.0f + __expf(-zv.x));
        y1 *= zv.y / (1.0f + __expf(-zv.y));
        y2 *= zv.z / (1.0f + __expf(-zv.z));
        y3 *= zv.w / (1.0f + __expf(-zv.w));
        *(float4*)(yp + c0) = make_float4(y0, y1, y2, y3);
    }
}

// ---------------------------------------------------------------------------
extern "C" void kernel_launch(void* const* d_in, const int* in_sizes, int n_in,
                              void* d_out, int out_size) {
    const float* x     = (const float*)d_in[0];
    const float* fe    = (const float*)d_in[1];
    const float* dw_w  = (const float*)d_in[2];
    const float* dw_b  = (const float*)d_in[3];
    const float* lin_w = (const float*)d_in[4];
    const float* lin_b = (const float*)d_in[5];
    const float* tok_w = (const float*)d_in[6];
    const float* tok_b = (const float*)d_in[7];
    const float* cc    = (const float*)d_in[8];
    const float* alpha = (const float*)d_in[9];
    const float* ln_g  = (const float*)d_in[10];
    const float* ln_b  = (const float*)d_in[11];
    const float* out_w = (const float*)d_in[12];
    const float* out_b = (const float*)d_in[13];
    float* out = (float*)d_out;

    // dynamic smem for DCT kernel (58 KB); idempotent, first call is
    // outside graph capture so the attribute is set before capture.
    cudaFuncSetAttribute(k_dct_mma, cudaFuncAttributeMaxDynamicSharedMemorySize,
                         DCT_SMEM_BYTES);

    k_dct_basis<<<64, 64>>>();
    k_dwconv<<<B_ * C_, 256>>>(x, dw_w, dw_b);
    k_gate_mma<<<dim3(32, 6), 256>>>(fe, tok_w, tok_b, cc, alpha);
    k_lin_mma<<<dim3(32, 12, B_), 256>>>(lin_w, lin_b);
    k_dct_mma<<<B_ * C_, 256, DCT_SMEM_BYTES>>>();
    k_ln<<<(B_ * HW_) / 16, 128>>>(ln_g, ln_b);
    k_out_mma<<<dim3(32, 6, B_), 256>>>(out_w, out_b, out);
}

// round 4
// speedup vs baseline: 2.7489x; 1.0076x over previous
#include <cuda_runtime.h>
#include <math.h>
#include <stdint.h>

#define B_ 8
#define C_ 384
#define HW_ 4096

// Scratch (device globals — no runtime allocation)
__device__ float g_buf0[B_ * C_ * HW_];   // xdw, later xi
__device__ float g_buf1[B_ * C_ * HW_];   // xs,  later y
__device__ float g_z[B_ * HW_ * C_];      // z token-major
__device__ float g_gate[C_ * HW_];        // spectral gate [c][n*64+k]
__device__ float g_W[64 * 64];            // DCT-II basis (Wh == Ww)

// ---------------------------------------------------------------------------
// helpers: tf32 conversion + m16n8k8 tf32 mma
// ---------------------------------------------------------------------------
__device__ __forceinline__ uint32_t f2tf(float f) {
    uint32_t u;
    asm("cvt.rna.tf32.f32 %0, %1;" : "=r"(u) : "f"(f));
    return u;
}

__device__ __forceinline__ void mma8(float* c, uint32_t a0, uint32_t a1,
                                     uint32_t a2, uint32_t a3,
                                     uint32_t b0, uint32_t b1) {
    asm volatile(
        "mma.sync.aligned.m16n8k8.row.col.f32.tf32.tf32.f32 "
        "{%0,%1,%2,%3}, {%4,%5,%6,%7}, {%8,%9}, {%0,%1,%2,%3};"
        : "+f"(c[0]), "+f"(c[1]), "+f"(c[2]), "+f"(c[3])
        : "r"(a0), "r"(a1), "r"(a2), "r"(a3), "r"(b0), "r"(b1));
}

// ---------------------------------------------------------------------------
// DCT basis
// ---------------------------------------------------------------------------
__global__ void k_dct_basis() {
    int n = blockIdx.x, x = threadIdx.x;
    float v = cosf((float)n * ((float)x + 0.5f) * (3.14159265358979323846f / 64.0f))
              * 0.17677669529663687f;
    if (n == 0) v *= 0.70710678118654752f;
    g_W[n * 64 + x] = v;
}

// ---------------------------------------------------------------------------
// Depthwise 3x3 conv (SAME) + bias. One block per (b,c) image.
// ---------------------------------------------------------------------------
__global__ void k_dwconv(const float* __restrict__ x,
                         const float* __restrict__ w,
                         const float* __restrict__ bias) {
    __shared__ float s[66 * 68];
    int bc = blockIdx.x;
    const float* xim = x + (size_t)bc * HW_;
    int tid = threadIdx.x;
    for (int i = tid; i < 66 * 66; i += 256) {
        int r = i / 66, cl = i % 66;
        int gh = r - 1, gw = cl - 1;
        float v = 0.0f;
        if ((unsigned)gh < 64u && (unsigned)gw < 64u) v = xim[gh * 64 + gw];
        s[r * 68 + cl] = v;
    }
    int c = bc % C_;
    const float* wp = w + c * 9;
    float w0 = wp[0], w1 = wp[1], w2 = wp[2];
    float w3 = wp[3], w4 = wp[4], w5 = wp[5];
    float w6 = wp[6], w7 = wp[7], w8 = wp[8];
    float bv = bias[c];
    __syncthreads();
    float* outp = g_buf0 + (size_t)bc * HW_;
    for (int p = tid; p < HW_; p += 256) {
        int h = p >> 6, ww = p & 63;
        const float* sp = s + h * 68 + ww;
        float acc = bv;
        acc = fmaf(sp[0],   w0, acc); acc = fmaf(sp[1],   w1, acc); acc = fmaf(sp[2],   w2, acc);
        acc = fmaf(sp[68],  w3, acc); acc = fmaf(sp[69],  w4, acc); acc = fmaf(sp[70],  w5, acc);
        acc = fmaf(sp[136], w6, acc); acc = fmaf(sp[137], w7, acc); acc = fmaf(sp[138], w8, acc);
        outp[p] = acc;
    }
}

// ===========================================================================
// GEMM core v2: block tile 128(M) x 128(N), 128 threads = 4 warps (2m x 2n),
// warp tile 64x64 (4 m-frags x 8 n-frags). K chunks of 32 (identical
// accumulation order to v1 -> bit-identical results).
// smem: sA [128][36] tf32, sB [128][36] (stride 36 -> conflict-free).
// AMODE 0: A gmem [K][M] (m contiguous); AMODE 1: A gmem [M][K].
// B gmem [N][K], k contiguous (ld = 384).
// ---------------------------------------------------------------------------
#define GSM_WORDS (2 * 128 * 36)   // 36864 B

template<int AMODE>
__device__ __forceinline__ void gemm_core(const float* __restrict__ Ag, int lda,
                                          const float* __restrict__ Bg,
                                          int m0, int n0, int tid,
                                          uint32_t* sm, float acc[4][8][4]) {
    uint32_t* sA = sm;                 // 128*36
    uint32_t* sB = sm + 128 * 36;      // 128*36
    int lane = tid & 31, g = lane >> 2, t4 = lane & 3;
    int warp = tid >> 5, wm = warp & 1, wn = warp >> 1;

    for (int kt = 0; kt < C_; kt += 32) {
        if (AMODE == 0) {
            #pragma unroll
            for (int j = 0; j < 8; j++) {
                int mm = tid, k4 = j;
                const float* p = Ag + (size_t)(kt + 4 * k4) * lda + m0 + mm;
                uint4 v;
                v.x = f2tf(p[0]);
                v.y = f2tf(p[lda]);
                v.z = f2tf(p[2 * lda]);
                v.w = f2tf(p[3 * lda]);
                *(uint4*)(sA + mm * 36 + 4 * k4) = v;
            }
        } else {
            #pragma unroll
            for (int j = 0; j < 8; j++) {
                int k4 = tid & 7, mm = (tid >> 3) + 16 * j;
                float4 f = *(const float4*)(Ag + (size_t)(m0 + mm) * lda + kt + 4 * k4);
                uint4 v;
                v.x = f2tf(f.x); v.y = f2tf(f.y); v.z = f2tf(f.z); v.w = f2tf(f.w);
                *(uint4*)(sA + mm * 36 + 4 * k4) = v;
            }
        }
        #pragma unroll
        for (int j = 0; j < 8; j++) {
            int k4 = tid & 7, nn = (tid >> 3) + 16 * j;
            float4 f = *(const float4*)(Bg + (size_t)(n0 + nn) * C_ + kt + 4 * k4);
            uint4 v;
            v.x = f2tf(f.x); v.y = f2tf(f.y); v.z = f2tf(f.z); v.w = f2tf(f.w);
            *(uint4*)(sB + nn * 36 + 4 * k4) = v;
        }
        __syncthreads();
        #pragma unroll
        for (int k8 = 0; k8 < 4; k8++) {
            uint32_t a[4][4], bq[8][2];
            #pragma unroll
            for (int mf = 0; mf < 4; mf++) {
                const uint32_t* pa = sA + (wm * 64 + mf * 16 + g) * 36 + k8 * 8 + t4;
                a[mf][0] = pa[0];
                a[mf][1] = pa[8 * 36];
                a[mf][2] = pa[4];
                a[mf][3] = pa[8 * 36 + 4];
            }
            #pragma unroll
            for (int nf = 0; nf < 8; nf++) {
                const uint32_t* pb = sB + (wn * 64 + nf * 8 + g) * 36 + k8 * 8 + t4;
                bq[nf][0] = pb[0];
                bq[nf][1] = pb[4];
            }
            #pragma unroll
            for (int mf = 0; mf < 4; mf++)
                #pragma unroll
                for (int nf = 0; nf < 8; nf++)
                    mma8(acc[mf][nf], a[mf][0], a[mf][1], a[mf][2], a[mf][3],
                         bq[nf][0], bq[nf][1]);
        }
        __syncthreads();
    }
}

// Chunked NCHW epilogue: 4 chunks of 32 channels, staged [ch][m] stride 132.
// F: functor(raw_value, global_channel) -> value to store.
template<typename F>
__device__ __forceinline__ void epi_nchw(uint32_t* sm, float acc[4][8][4],
                                         int tid, float* dst, int strideM,
                                         int m0, int n0, F f) {
    float* sC = (float*)sm;
    int lane = tid & 31, g = lane >> 2, t4 = lane & 3;
    int warp = tid >> 5, wm = warp & 1, wn = warp >> 1;
    #pragma unroll
    for (int c = 0; c < 4; c++) {
        if (wn == (c >> 1)) {
            int nf0 = 4 * (c & 1);
            #pragma unroll
            for (int mf = 0; mf < 4; mf++) {
                int r = wm * 64 + mf * 16 + g;
                #pragma unroll
                for (int nfl = 0; nfl < 4; nfl++) {
                    int nf = nf0 + nfl;
                    int chl = nfl * 8 + 2 * t4;
                    sC[chl * 132 + r]           = acc[mf][nf][0];
                    sC[(chl + 1) * 132 + r]     = acc[mf][nf][1];
                    sC[chl * 132 + r + 8]       = acc[mf][nf][2];
                    sC[(chl + 1) * 132 + r + 8] = acc[mf][nf][3];
                }
            }
        }
        __syncthreads();
        for (int i = tid; i < 4096; i += 128) {
            int ch = i >> 7, mm = i & 127;
            int gc = n0 + 32 * c + ch;
            dst[(size_t)gc * strideM + m0 + mm] = f(sC[ch * 132 + mm], gc);
        }
        __syncthreads();
    }
}

// ---------------------------------------------------------------------------
// lin GEMM: xz[m][d] = sum_c xdw[c][m]*lin_w[d][c] + lin_b[d]
// by 0..2 -> xs (NCHW); by 3..5 -> z (token-major)
// ---------------------------------------------------------------------------
struct AddBias {
    const float* b;
    __device__ float operator()(float v, int ch) const { return v + b[ch]; }
};

__global__ void __launch_bounds__(128) k_lin_mma(const float* __restrict__ lw,
                                                const float* __restrict__ lb) {
    __shared__ __align__(16) uint32_t sm[GSM_WORDS];
    int tid = threadIdx.x;
    int b = blockIdx.z, m0 = blockIdx.x * 128, n0 = blockIdx.y * 128;
    float acc[4][8][4];
    #pragma unroll
    for (int i = 0; i < 4; i++)
        #pragma unroll
        for (int j = 0; j < 8; j++)
            #pragma unroll
            for (int k = 0; k < 4; k++) acc[i][j][k] = 0.0f;

    gemm_core<0>(g_buf0 + (size_t)b * C_ * HW_, HW_, lw, m0, n0, tid, sm, acc);

    if (n0 < C_) {
        epi_nchw(sm, acc, tid, g_buf1 + (size_t)b * C_ * HW_, HW_, m0, n0,
                 AddBias{lb});
    } else {
        // z half -> token-major [m][C_], chunked over m (2 chunks of 64 rows)
        float* sC = (float*)sm;
        int lane = tid & 31, g = lane >> 2, t4 = lane & 3;
        int warp = tid >> 5, wm = warp & 1, wn = warp >> 1;
        float* zb = g_z + (size_t)b * HW_ * C_;
        int zoff = n0 - C_;
        #pragma unroll
        for (int j = 0; j < 2; j++) {
            if (wm == j) {
                #pragma unroll
                for (int mf = 0; mf < 4; mf++) {
                    int rl = mf * 16 + g;
                    #pragma unroll
                    for (int nf = 0; nf < 8; nf++) {
                        int cc = wn * 64 + nf * 8 + 2 * t4;
                        *(float2*)(sC + rl * 132 + cc) =
                            make_float2(acc[mf][nf][0], acc[mf][nf][1]);
                        *(float2*)(sC + (rl + 8) * 132 + cc) =
                            make_float2(acc[mf][nf][2], acc[mf][nf][3]);
                    }
                }
            }
            __syncthreads();
            for (int i = tid; i < 2048; i += 128) {
                int row = i >> 5, q = i & 31;
                float4 v = *(float4*)(sC + row * 132 + 4 * q);
                float4 bb = *(const float4*)(lb + C_ + zoff + 4 * q);
                v.x += bb.x; v.y += bb.y; v.z += bb.z; v.w += bb.w;
                *(float4*)(zb + (size_t)(m0 + 64 * j + row) * C_ + zoff + 4 * q) = v;
            }
            __syncthreads();
        }
    }
}

// ---------------------------------------------------------------------------
// gate GEMM: t = relu(fe @ tok_w^T + tok_b); gate = cos(c*t)+sin(c*t)*(1+.5a)/c
// ---------------------------------------------------------------------------
struct GateXform {
    const float* tb;
    float c0, s1;
    __device__ float operator()(float v, int ch) const {
        float t = fmaxf(v + tb[ch], 0.0f);
        float ct = c0 * t;
        return cosf(ct) + sinf(ct) * s1;
    }
};

__global__ void __launch_bounds__(128) k_gate_mma(const float* __restrict__ fe,
                                                  const float* __restrict__ tw,
                                                  const float* __restrict__ tb,
                                                  const float* __restrict__ cp,
                                                  const float* __restrict__ ap) {
    __shared__ __align__(16) uint32_t sm[GSM_WORDS];
    int tid = threadIdx.x;
    int m0 = blockIdx.x * 128, n0 = blockIdx.y * 128;
    float acc[4][8][4];
    #pragma unroll
    for (int i = 0; i < 4; i++)
        #pragma unroll
        for (int j = 0; j < 8; j++)
            #pragma unroll
            for (int k = 0; k < 4; k++) acc[i][j][k] = 0.0f;

    gemm_core<1>(fe, C_, tw, m0, n0, tid, sm, acc);

    float c0 = cp[0];
    float s1 = (1.0f + 0.5f * ap[0]) / c0;
    epi_nchw(sm, acc, tid, g_gate, HW_, m0, n0, GateXform{tb, c0, s1});
}

// ---------------------------------------------------------------------------
// out GEMM: out[d][m] = sum_c y[m][c]*out_w[d][c] + out_b[d]
// ---------------------------------------------------------------------------
__global__ void __launch_bounds__(128) k_out_mma(const float* __restrict__ ow,
                                                 const float* __restrict__ ob,
                                                 float* __restrict__ out) {
    __shared__ __align__(16) uint32_t sm[GSM_WORDS];
    int tid = threadIdx.x;
    int b = blockIdx.z, m0 = blockIdx.x * 128, n0 = blockIdx.y * 128;
    float acc[4][8][4];
    #pragma unroll
    for (int i = 0; i < 4; i++)
        #pragma unroll
        for (int j = 0; j < 8; j++)
            #pragma unroll
            for (int k = 0; k < 4; k++) acc[i][j][k] = 0.0f;

    gemm_core<1>(g_buf1 + (size_t)b * HW_ * C_, C_, ow, m0, n0, tid, sm, acc);

    epi_nchw(sm, acc, tid, out + (size_t)b * C_ * HW_, HW_, m0, n0, AddBias{ob});
}

// ===========================================================================
// Fused DCT -> gate -> iDCT, 2 images per block (shared W tile).
// 8 warps: img = warp>>2; within image 4 warps (wm=warp&1 rows, wn cols),
// warp tile 32x32 (2 m-frags x 4 n-frags). Same per-element K order as v1.
// ---------------------------------------------------------------------------
#define DS 76
#define DTILE (64 * DS)
#define DCT_SMEM_BYTES (5 * DTILE * 4)   // W + 2*(A,B) = 97280 B

__device__ __forceinline__ void dct_mm2(const uint32_t* __restrict__ pA,
                                        const uint32_t* __restrict__ pB,
                                        float acc[2][4][4], int rb, int nb,
                                        int g, int t4) {
    #pragma unroll
    for (int mf = 0; mf < 2; mf++)
        #pragma unroll
        for (int nf = 0; nf < 4; nf++)
            #pragma unroll
            for (int j = 0; j < 4; j++) acc[mf][nf][j] = 0.0f;
    #pragma unroll
    for (int k8 = 0; k8 < 8; k8++) {
        uint32_t a[2][4];
        #pragma unroll
        for (int mf = 0; mf < 2; mf++) {
            const uint32_t* pa = pA + (rb + mf * 16 + g) * DS + k8 * 8 + t4;
            a[mf][0] = pa[0];
            a[mf][1] = pa[8 * DS];
            a[mf][2] = pa[4];
            a[mf][3] = pa[8 * DS + 4];
        }
        #pragma unroll
        for (int nf = 0; nf < 4; nf++) {
            int n = nb + nf * 8 + g;
            uint32_t b0 = pB[(k8 * 8 + t4) * DS + n];
            uint32_t b1 = pB[(k8 * 8 + t4 + 4) * DS + n];
            mma8(acc[0][nf], a[0][0], a[0][1], a[0][2], a[0][3], b0, b1);
            mma8(acc[1][nf], a[1][0], a[1][1], a[1][2], a[1][3], b0, b1);
        }
    }
}

__global__ void __launch_bounds__(256) k_dct_mma() {
    extern __shared__ uint32_t dsm[];
    uint32_t* tW = dsm;
    int tid = threadIdx.x;
    int lane = tid & 31, g = lane >> 2, t4 = lane & 3;
    int warp = tid >> 5;
    int img = warp >> 2, w4 = warp & 3;
    int wm = w4 & 1, wn = w4 >> 1;
    int rb = wm * 32, nb = wn * 32;

    // load W + both images
    for (int i = tid; i < 4096; i += 256)
        tW[(i >> 6) * DS + (i & 63)] = f2tf(g_W[i]);
    for (int i = tid; i < 8192; i += 256) {
        int im = i >> 12, idx = i & 4095;
        const float* xim = g_buf1 + (size_t)(blockIdx.x * 2 + im) * HW_;
        dsm[DTILE * (1 + 2 * im) + (idx >> 6) * DS + (idx & 63)] = f2tf(xim[idx]);
    }
    __syncthreads();

    uint32_t* tA = dsm + DTILE * (1 + 2 * img);
    uint32_t* tB = tA + DTILE;
    int bc = blockIdx.x * 2 + img;
    int c = bc % C_;
    float acc[2][4][4];

    // mm1: M1[n][w] = sum_h W[n][h] X[h][w]  -> tB transposed [w][n]
    dct_mm2(tW, tA, acc, rb, nb, g, t4);
    #pragma unroll
    for (int mf = 0; mf < 2; mf++) {
        int r = rb + mf * 16 + g;
        #pragma unroll
        for (int nf = 0; nf < 4; nf++) {
            int cc = nb + nf * 8 + 2 * t4;
            tB[cc * DS + r]           = f2tf(acc[mf][nf][0]);
            tB[(cc + 1) * DS + r]     = f2tf(acc[mf][nf][1]);
            tB[cc * DS + r + 8]       = f2tf(acc[mf][nf][2]);
            tB[(cc + 1) * DS + r + 8] = f2tf(acc[mf][nf][3]);
        }
    }
    __syncthreads();

    // mm2: XdT[k][n] = sum_w W[k][w] M1T[w][n]; gate; -> tA [k][n]
    dct_mm2(tW, tB, acc, rb, nb, g, t4);
    {
        const float* gp = g_gate + (size_t)c * HW_;
        #pragma unroll
        for (int mf = 0; mf < 2; mf++) {
            int r = rb + mf * 16 + g;
            #pragma unroll
            for (int nf = 0; nf < 4; nf++) {
                int cc = nb + nf * 8 + 2 * t4;
                float g0 = gp[cc * 64 + r];
                float g1 = gp[(cc + 1) * 64 + r];
                float g2 = gp[cc * 64 + r + 8];
                float g3 = gp[(cc + 1) * 64 + r + 8];
                tA[r * DS + cc]           = f2tf(acc[mf][nf][0] * g0);
                tA[r * DS + cc + 1]       = f2tf(acc[mf][nf][1] * g1);
                tA[(r + 8) * DS + cc]     = f2tf(acc[mf][nf][2] * g2);
                tA[(r + 8) * DS + cc + 1] = f2tf(acc[mf][nf][3] * g3);
            }
        }
    }
    __syncthreads();

    // mm3: M2T[k][h] = sum_n F[k][n] W[n][h] -> tB transposed [h][k]
    dct_mm2(tA, tW, acc, rb, nb, g, t4);
    #pragma unroll
    for (int mf = 0; mf < 2; mf++) {
        int r = rb + mf * 16 + g;
        #pragma unroll
        for (int nf = 0; nf < 4; nf++) {
            int cc = nb + nf * 8 + 2 * t4;
            tB[cc * DS + r]           = f2tf(acc[mf][nf][0]);
            tB[(cc + 1) * DS + r]     = f2tf(acc[mf][nf][1]);
            tB[cc * DS + r + 8]       = f2tf(acc[mf][nf][2]);
            tB[(cc + 1) * DS + r + 8] = f2tf(acc[mf][nf][3]);
        }
    }
    __syncthreads();

    // mm4: xi[h][w] = sum_k M2T[k][h] W[k][w] -> gmem
    dct_mm2(tB, tW, acc, rb, nb, g, t4);
    float* xo = g_buf0 + (size_t)bc * HW_;
    #pragma unroll
    for (int mf = 0; mf < 2; mf++) {
        int r = rb + mf * 16 + g;
        #pragma unroll
        for (int nf = 0; nf < 4; nf++) {
            int cc = nb + nf * 8 + 2 * t4;
            *(float2*)(xo + r * 64 + cc)       = make_float2(acc[mf][nf][0], acc[mf][nf][1]);
            *(float2*)(xo + (r + 8) * 64 + cc) = make_float2(acc[mf][nf][2], acc[mf][nf][3]);
        }
    }
}

// ---------------------------------------------------------------------------
// LayerNorm over channels + SiLU(z) gate. 16 tokens per block of 128 threads.
// ---------------------------------------------------------------------------
__global__ void k_ln(const float* __restrict__ lng, const float* __restrict__ lnb) {
    __shared__ float s[C_ * 17];
    int tid = threadIdx.x;
    int mglob = blockIdx.x * 16;
    int b = mglob >> 12;
    int mloc = mglob & 4095;
    const float* xi = g_buf0 + (size_t)b * C_ * HW_ + mloc;
    for (int i = tid; i < C_ * 16; i += 128) {
        int cc = i >> 4, t = i & 15;
        s[cc * 17 + t] = xi[(size_t)cc * HW_ + t];
    }
    __syncthreads();
    int tk = tid >> 3, g = tid & 7;
    float sum = 0.0f, ss = 0.0f;
    #pragma unroll 8
    for (int ii = 0; ii < 48; ii++) {
        int cc = g + ii * 8;
        float v = s[cc * 17 + tk];
        sum += v; ss += v * v;
    }
    #pragma unroll
    for (int off = 4; off; off >>= 1) {
        sum += __shfl_down_sync(0xffffffffu, sum, off);
        ss  += __shfl_down_sync(0xffffffffu, ss,  off);
    }
    int lane = tid & 31;
    int src = lane & ~7;
    sum = __shfl_sync(0xffffffffu, sum, src);
    ss  = __shfl_sync(0xffffffffu, ss,  src);
    float mu = sum * (1.0f / 384.0f);
    float var = ss * (1.0f / 384.0f) - mu * mu;
    float rstd = rsqrtf(fmaxf(var, 0.0f) + 1e-5f);

    int mt = mloc + tk;
    const float* zp = g_z + ((size_t)b * HW_ + mt) * C_;
    float* yp = g_buf1 + ((size_t)b * HW_ + mt) * C_;
    #pragma unroll 4
    for (int ii = 0; ii < 12; ii++) {
        int c0 = g * 48 + ii * 4;
        float4 zv = *(const float4*)(zp + c0);
        float4 gg = *(const float4*)(lng + c0);
        float4 bb = *(const float4*)(lnb + c0);
        float y0 = (s[(c0 + 0) * 17 + tk] - mu) * rstd * gg.x + bb.x;
        float y1 = (s[(c0 + 1) * 17 + tk] - mu) * rstd * gg.y + bb.y;
        float y2 = (s[(c0 + 2) * 17 + tk] - mu) * rstd * gg.z + bb.z;
        float y3 = (s[(c0 + 3) * 17 + tk] - mu) * rstd * gg.w + bb.w;
        y0 *= zv.x / (1.0f + __expf(-zv.x));
        y1 *= zv.y / (1.0f + __expf(-zv.y));
        y2 *= zv.z / (1.0f + __expf(-zv.z));
        y3 *= zv.w / (1.0f + __expf(-zv.w));
        *(float4*)(yp + c0) = make_float4(y0, y1, y2, y3);
    }
}

// ---------------------------------------------------------------------------
extern "C" void kernel_launch(void* const* d_in, const int* in_sizes, int n_in,
                              void* d_out, int out_size) {
    const float* x     = (const float*)d_in[0];
    const float* fe    = (const float*)d_in[1];
    const float* dw_w  = (const float*)d_in[2];
    const float* dw_b  = (const float*)d_in[3];
    const float* lin_w = (const float*)d_in[4];
    const float* lin_b = (const float*)d_in[5];
    const float* tok_w = (const float*)d_in[6];
    const float* tok_b = (const float*)d_in[7];
    const float* cc    = (const float*)d_in[8];
    const float* alpha = (const float*)d_in[9];
    const float* ln_g  = (const float*)d_in[10];
    const float* ln_b  = (const float*)d_in[11];
    const float* out_w = (const float*)d_in[12];
    const float* out_b = (const float*)d_in[13];
    float* out = (float*)d_out;

    cudaFuncSetAttribute(k_dct_mma, cudaFuncAttributeMaxDynamicSharedMemorySize,
                         DCT_SMEM_BYTES);

    k_dct_basis<<<64, 64>>>();
    k_dwconv<<<B_ * C_, 256>>>(x, dw_w, dw_b);
    k_gate_mma<<<dim3(32, 3), 128>>>(fe, tok_w, tok_b, cc, alpha);
    k_lin_mma<<<dim3(32, 6, B_), 128>>>(lin_w, lin_b);
    k_dct_mma<<<(B_ * C_) / 2, 256, DCT_SMEM_BYTES>>>();
    k_ln<<<(B_ * HW_) / 16, 128>>>(ln_g, ln_b);
    k_out_mma<<<dim3(32, 3, B_), 128>>>(out_w, out_b, out);
}